// round 7
// baseline (speedup 1.0000x reference)
#include <cuda_runtime.h>
#include <stdint.h>

#define P1 2654435761u
#define P2 805459861u

// 256-bit feature-row gather with L2 evict_last (sm_100a requires v8.b32 for
// the eviction hint — exactly one 32B feature row per load).
__device__ __forceinline__ void ldg256_el(const float* p, float* d) {
    unsigned r0, r1, r2, r3, r4, r5, r6, r7;
    asm volatile(
        "ld.global.nc.L2::evict_last.v8.b32 {%0,%1,%2,%3,%4,%5,%6,%7}, [%8];"
        : "=r"(r0), "=r"(r1), "=r"(r2), "=r"(r3),
          "=r"(r4), "=r"(r5), "=r"(r6), "=r"(r7)
        : "l"(p));
    d[0] = __uint_as_float(r0); d[1] = __uint_as_float(r1);
    d[2] = __uint_as_float(r2); d[3] = __uint_as_float(r3);
    d[4] = __uint_as_float(r4); d[5] = __uint_as_float(r5);
    d[6] = __uint_as_float(r6); d[7] = __uint_as_float(r7);
}

// Streaming point load: evict-first so it doesn't displace table lines.
__device__ __forceinline__ float ldg_stream(const float* p) {
    float v;
    asm volatile("ld.global.cs.f32 %0, [%1];" : "=f"(v) : "l"(p));
    return v;
}

// Streaming store: evict-first.
__device__ __forceinline__ void stg_stream(float4* p, float4 v) {
    asm volatile("st.global.cs.v4.f32 [%0], {%1,%2,%3,%4};"
                 :: "l"(p), "f"(v.x), "f"(v.y), "f"(v.z), "f"(v.w) : "memory");
}

template <bool POW2>
__global__ __launch_bounds__(256)
void hash_interp_256(const float* __restrict__ pts,
                     const float* __restrict__ feat,
                     float* __restrict__ out,
                     int n, unsigned buckets, unsigned mask)
{
    const int i = blockIdx.x * blockDim.x + threadIdx.x;
    if (i >= n) return;

    const float px = ldg_stream(pts + 3 * (size_t)i + 0);
    const float py = ldg_stream(pts + 3 * (size_t)i + 1);
    const float pz = ldg_stream(pts + 3 * (size_t)i + 2);

    // continuous grid coords, matching reference's pts / 0.005
    const float qx = px / 0.005f;
    const float qy = py / 0.005f;
    const float qz = pz / 0.005f;

    const float bxf = floorf(qx);
    const float byf = floorf(qy);
    const float bzf = floorf(qz);
    const int bx = (int)bxf, by = (int)byf, bz = (int)bzf;

    const float fx = qx - bxf;
    const float fy = qy - byf;
    const float fz = qz - bzf;

    // per-axis hash terms
    const unsigned hx0 = (unsigned)bx;           // * 1
    const unsigned hx1 = (unsigned)(bx + 1);
    const unsigned hy0 = (unsigned)by * P1;
    const unsigned hy1 = hy0 + P1;
    const unsigned hz0 = (unsigned)bz * P2;
    const unsigned hz1 = hz0 + P2;

    unsigned slot[8];
    {
        const unsigned s0 = hx0 ^ hy0 ^ hz0;
        const unsigned s1 = hx1 ^ hy0 ^ hz0;
        const unsigned s2 = hx0 ^ hy1 ^ hz0;
        const unsigned s3 = hx1 ^ hy1 ^ hz0;
        const unsigned s4 = hx0 ^ hy0 ^ hz1;
        const unsigned s5 = hx1 ^ hy0 ^ hz1;
        const unsigned s6 = hx0 ^ hy1 ^ hz1;
        const unsigned s7 = hx1 ^ hy1 ^ hz1;
        if (POW2) {
            slot[0] = s0 & mask; slot[1] = s1 & mask; slot[2] = s2 & mask; slot[3] = s3 & mask;
            slot[4] = s4 & mask; slot[5] = s5 & mask; slot[6] = s6 & mask; slot[7] = s7 & mask;
        } else {
            slot[0] = s0 % buckets; slot[1] = s1 % buckets; slot[2] = s2 % buckets; slot[3] = s3 % buckets;
            slot[4] = s4 % buckets; slot[5] = s5 % buckets; slot[6] = s6 % buckets; slot[7] = s7 % buckets;
        }
    }

    // 8 x 256-bit gathers, all issued before consumption for max MLP
    float v[8][8];
#pragma unroll
    for (int c = 0; c < 8; c++) {
        ldg256_el(feat + (size_t)slot[c] * 8, v[c]);
    }

    // trilinear weights (same multiply order as reference)
    const float wx0 = 1.0f - fx, wx1 = fx;
    const float wy0 = 1.0f - fy, wy1 = fy;
    const float wz0 = 1.0f - fz, wz1 = fz;
    float w[8];
    w[0] = wx0 * wy0 * wz0;
    w[1] = wx1 * wy0 * wz0;
    w[2] = wx0 * wy1 * wz0;
    w[3] = wx1 * wy1 * wz0;
    w[4] = wx0 * wy0 * wz1;
    w[5] = wx1 * wy0 * wz1;
    w[6] = wx0 * wy1 * wz1;
    w[7] = wx1 * wy1 * wz1;

    float a[8] = {0.f, 0.f, 0.f, 0.f, 0.f, 0.f, 0.f, 0.f};
#pragma unroll
    for (int c = 0; c < 8; c++) {
        const float wc = w[c];
#pragma unroll
        for (int d = 0; d < 8; d++) {
            a[d] = fmaf(wc, v[c][d], a[d]);
        }
    }

    float4* op = reinterpret_cast<float4*>(out + (size_t)i * 8);
    stg_stream(op + 0, make_float4(a[0], a[1], a[2], a[3]));
    stg_stream(op + 1, make_float4(a[4], a[5], a[6], a[7]));
}

extern "C" void kernel_launch(void* const* d_in, const int* in_sizes, int n_in,
                              void* d_out, int out_size)
{
    const float* pts  = (const float*)d_in[0];
    const float* feat = (const float*)d_in[1];
    float* out = (float*)d_out;

    int n = in_sizes[0] / 3;
    unsigned buckets = (unsigned)(in_sizes[1] / 8);
    unsigned mask = buckets - 1u;
    bool pow2 = (buckets & (buckets - 1u)) == 0u;

    int threads = 256;
    int blocks = (n + threads - 1) / threads;

    if (pow2) {
        hash_interp_256<true><<<blocks, threads>>>(pts, feat, out, n, buckets, mask);
    } else {
        hash_interp_256<false><<<blocks, threads>>>(pts, feat, out, n, buckets, mask);
    }
}

// round 8
// speedup vs baseline: 1.0735x; 1.0735x over previous
#include <cuda_runtime.h>
#include <stdint.h>

#define P1 2654435761u
#define P2 805459861u

// Policy-carrying 16B table gather (cache_hint form works at any width).
__device__ __forceinline__ float4 ldg_table_pol(const float4* p, uint64_t pol) {
    float4 v;
    asm volatile("ld.global.nc.L2::cache_hint.v4.f32 {%0,%1,%2,%3}, [%4], %5;"
                 : "=f"(v.x), "=f"(v.y), "=f"(v.z), "=f"(v.w)
                 : "l"(p), "l"(pol));
    return v;
}

// Streaming point load: evict-first so it doesn't displace pinned table lines.
__device__ __forceinline__ float ldg_stream(const float* p) {
    float v;
    asm volatile("ld.global.cs.f32 %0, [%1];" : "=f"(v) : "l"(p));
    return v;
}

// Streaming store: evict-first.
__device__ __forceinline__ void stg_stream(float4* p, float4 v) {
    asm volatile("st.global.cs.v4.f32 [%0], {%1,%2,%3,%4};"
                 :: "l"(p), "f"(v.x), "f"(v.y), "f"(v.z), "f"(v.w) : "memory");
}

// 2 lanes per point (best measured layout): lane 2k+h handles point k, half h
// of the 32B feature row; pair-lanes share each 128B line -> 8 wf/point.
// L2 policy: slots < pin_limit (3/4 of table, ~100MB, fits L2) are loaded
// evict_last -> stable resident set across graph replays; the rest evict_first.
template <bool POW2>
__global__ __launch_bounds__(256)
void hash_interp_pin(const float* __restrict__ pts,
                     const float* __restrict__ feat,
                     float* __restrict__ out,
                     int n, unsigned buckets, unsigned mask, unsigned pin_limit)
{
    uint64_t pol_keep, pol_stream;
    asm("createpolicy.fractional.L2::evict_last.b64 %0, 1.0;"  : "=l"(pol_keep));
    asm("createpolicy.fractional.L2::evict_first.b64 %0, 1.0;" : "=l"(pol_stream));

    const unsigned lane = threadIdx.x & 31u;
    const int gwarp = (int)((blockIdx.x * blockDim.x + threadIdx.x) >> 5);

    const int p_raw = gwarp * 16 + (int)(lane >> 1);   // 16 points per warp
    const bool valid = (p_raw < n);
    const int p = valid ? p_raw : 0;
    const unsigned h = lane & 1u;                      // 16B half of the row

    // point coords (pair-lanes read identical addresses -> broadcast)
    const float px = ldg_stream(pts + 3 * (size_t)p + 0);
    const float py = ldg_stream(pts + 3 * (size_t)p + 1);
    const float pz = ldg_stream(pts + 3 * (size_t)p + 2);

    // continuous grid coords, matching reference's pts / 0.005
    const float qx = px / 0.005f;
    const float qy = py / 0.005f;
    const float qz = pz / 0.005f;

    const float bxf = floorf(qx);
    const float byf = floorf(qy);
    const float bzf = floorf(qz);
    const int bx = (int)bxf, by = (int)byf, bz = (int)bzf;

    const float fx = qx - bxf;
    const float fy = qy - byf;
    const float fz = qz - bzf;

    // per-axis hash terms
    const unsigned hx0 = (unsigned)bx;           // * 1
    const unsigned hx1 = (unsigned)(bx + 1);
    const unsigned hy0 = (unsigned)by * P1;
    const unsigned hy1 = hy0 + P1;
    const unsigned hz0 = (unsigned)bz * P2;
    const unsigned hz1 = hz0 + P2;

    unsigned slot[8];
    {
        const unsigned s0 = hx0 ^ hy0 ^ hz0;
        const unsigned s1 = hx1 ^ hy0 ^ hz0;
        const unsigned s2 = hx0 ^ hy1 ^ hz0;
        const unsigned s3 = hx1 ^ hy1 ^ hz0;
        const unsigned s4 = hx0 ^ hy0 ^ hz1;
        const unsigned s5 = hx1 ^ hy0 ^ hz1;
        const unsigned s6 = hx0 ^ hy1 ^ hz1;
        const unsigned s7 = hx1 ^ hy1 ^ hz1;
        if (POW2) {
            slot[0] = s0 & mask; slot[1] = s1 & mask; slot[2] = s2 & mask; slot[3] = s3 & mask;
            slot[4] = s4 & mask; slot[5] = s5 & mask; slot[6] = s6 & mask; slot[7] = s7 & mask;
        } else {
            slot[0] = s0 % buckets; slot[1] = s1 % buckets; slot[2] = s2 % buckets; slot[3] = s3 % buckets;
            slot[4] = s4 % buckets; slot[5] = s5 % buckets; slot[6] = s6 % buckets; slot[7] = s7 % buckets;
        }
    }

    // issue all 8 gathers up-front for MLP; pair-lanes share each 128B line
    const float4* fbase = reinterpret_cast<const float4*>(feat);
    float4 v[8];
#pragma unroll
    for (int c = 0; c < 8; c++) {
        const uint64_t pol = (slot[c] < pin_limit) ? pol_keep : pol_stream;
        v[c] = ldg_table_pol(fbase + ((size_t)slot[c] * 2 + h), pol);
    }

    // trilinear weights (same multiply order as reference); after the loads so
    // the ALU overlaps memory latency.
    const float wx0 = 1.0f - fx, wx1 = fx;
    const float wy0 = 1.0f - fy, wy1 = fy;
    const float wz0 = 1.0f - fz, wz1 = fz;
    float w[8];
    w[0] = wx0 * wy0 * wz0;
    w[1] = wx1 * wy0 * wz0;
    w[2] = wx0 * wy1 * wz0;
    w[3] = wx1 * wy1 * wz0;
    w[4] = wx0 * wy0 * wz1;
    w[5] = wx1 * wy0 * wz1;
    w[6] = wx0 * wy1 * wz1;
    w[7] = wx1 * wy1 * wz1;

    float a0 = 0.f, a1 = 0.f, a2 = 0.f, a3 = 0.f;
#pragma unroll
    for (int c = 0; c < 8; c++) {
        const float wc = w[c];
        a0 = fmaf(wc, v[c].x, a0);
        a1 = fmaf(wc, v[c].y, a1);
        a2 = fmaf(wc, v[c].z, a2);
        a3 = fmaf(wc, v[c].w, a3);
    }

    if (valid) {
        stg_stream(reinterpret_cast<float4*>(out) + ((size_t)p_raw * 2 + h),
                   make_float4(a0, a1, a2, a3));
    }
}

extern "C" void kernel_launch(void* const* d_in, const int* in_sizes, int n_in,
                              void* d_out, int out_size)
{
    const float* pts  = (const float*)d_in[0];
    const float* feat = (const float*)d_in[1];
    float* out = (float*)d_out;

    int n = in_sizes[0] / 3;
    unsigned buckets = (unsigned)(in_sizes[1] / 8);
    unsigned mask = buckets - 1u;
    bool pow2 = (buckets & (buckets - 1u)) == 0u;

    // Pin the lower 3/4 of the table (~100MB) in L2; leave headroom for streams.
    unsigned pin_limit = (unsigned)(((unsigned long long)buckets * 3ull) / 4ull);

    // 2 lanes per point -> 16 points per warp
    long long warps = ((long long)n + 15) / 16;
    long long threads_total = warps * 32;
    int threads = 256;
    int blocks = (int)((threads_total + threads - 1) / threads);

    if (pow2) {
        hash_interp_pin<true><<<blocks, threads>>>(pts, feat, out, n, buckets, mask, pin_limit);
    } else {
        hash_interp_pin<false><<<blocks, threads>>>(pts, feat, out, n, buckets, mask, pin_limit);
    }
}